// round 2
// baseline (speedup 1.0000x reference)
#include <cuda_runtime.h>
#include <math.h>

#define HGT   64
#define WID   64
#define CH    256
#define BATCH 4
#define HW    (HGT*WID)
#define RAD   3
#define NK    49
#define PXB   32          // pixels per block (half row)
#define NCB   (PXB+6)     // 38 neighborhood columns
#define X2ROWS (7*NCB)    // 266
#define CHUNK 32
#define STR   36          // smem row stride (floats), 16B-aligned
#define WSTR  52

// Pixel-major scratch: [B][HW][C]
__device__ float g_q[BATCH*HW*CH];
__device__ float g_k[BATCH*HW*CH];
__device__ float g_v[BATCH*HW*CH];

// ---------------------------------------------------------------------------
// GEMM: Yt[b][p][o] = sum_c X[b][c][p] * W[o][c]   (unchanged from R1)
// ---------------------------------------------------------------------------
__global__ __launch_bounds__(256) void gemm_kernel(
    const float* __restrict__ x,
    const float* __restrict__ w1,
    const float* __restrict__ w2,
    const float* __restrict__ w3)
{
    const int z    = blockIdx.z;
    const int b    = z / 3;
    const int wsel = z - b*3;
    const float* W = (wsel == 0) ? w1 : (wsel == 1 ? w2 : w3);
    float* Y       = (wsel == 0) ? g_q : (wsel == 1 ? g_k : g_v);
    const float* X = x + (size_t)b * CH * HW;
    Y += (size_t)b * HW * CH;

    const int p0 = blockIdx.x * 128;
    const int o0 = blockIdx.y * 64;

    __shared__ float As[16][128];
    __shared__ float Bs[16][68];

    const int tid = threadIdx.x;
    const int tx  = tid & 15;
    const int ty  = tid >> 4;

    float acc[8][4];
#pragma unroll
    for (int i = 0; i < 8; i++)
#pragma unroll
        for (int j = 0; j < 4; j++) acc[i][j] = 0.f;

    for (int k0 = 0; k0 < CH; k0 += 16) {
#pragma unroll
        for (int r = 0; r < 2; r++) {
            int idx = tid + r * 256;
            int cr  = idx >> 5;
            int p4  = (idx & 31) << 2;
            float4 v = *(const float4*)(X + (size_t)(k0 + cr) * HW + p0 + p4);
            *(float4*)(&As[cr][p4]) = v;
        }
        {
            int oo  = tid >> 2;
            int kk4 = (tid & 3) << 2;
            float4 v = *(const float4*)(W + (size_t)(o0 + oo) * CH + k0 + kk4);
            Bs[kk4 + 0][oo] = v.x;
            Bs[kk4 + 1][oo] = v.y;
            Bs[kk4 + 2][oo] = v.z;
            Bs[kk4 + 3][oo] = v.w;
        }
        __syncthreads();

#pragma unroll
        for (int kk = 0; kk < 16; kk++) {
            float a[8], bb[4];
            float4 a0 = *(const float4*)(&As[kk][ty * 8]);
            float4 a1 = *(const float4*)(&As[kk][ty * 8 + 4]);
            a[0]=a0.x; a[1]=a0.y; a[2]=a0.z; a[3]=a0.w;
            a[4]=a1.x; a[5]=a1.y; a[6]=a1.z; a[7]=a1.w;
            float4 b0 = *(const float4*)(&Bs[kk][tx * 4]);
            bb[0]=b0.x; bb[1]=b0.y; bb[2]=b0.z; bb[3]=b0.w;
#pragma unroll
            for (int i = 0; i < 8; i++)
#pragma unroll
                for (int j = 0; j < 4; j++)
                    acc[i][j] = fmaf(a[i], bb[j], acc[i][j]);
        }
        __syncthreads();
    }

#pragma unroll
    for (int i = 0; i < 8; i++) {
        float4 v = make_float4(acc[i][0], acc[i][1], acc[i][2], acc[i][3]);
        *(float4*)(Y + (size_t)(p0 + ty * 8 + i) * CH + o0 + tx * 4) = v;
    }
}

// ---------------------------------------------------------------------------
// Attention: one block per (b, h, half-row). 256 threads, ~49.6KB smem.
// Phase 1: 8 threads/pixel, float4 LDS, 7 logits each; 8-lane shfl softmax.
// Phase 2: thread=channel, 32 register accumulators, one LDG per v element.
// smem floats: ws[32*52]=1664 | x1s[32*36]=1152 | x2s[266*36]=9576 = 12392
//              outS[256*33]=8448 aliases x1s+x2s.
// ---------------------------------------------------------------------------
#define WS_OFF   0
#define X1_OFF   1664
#define X2_OFF   (1664+1152)
#define OUTS_OFF 1664
#define SMEM_FLOATS 12392

__global__ __launch_bounds__(256, 4) void attn_kernel(float* __restrict__ out)
{
    extern __shared__ float smem[];
    float* ws   = smem + WS_OFF;
    float* x1s  = smem + X1_OFF;
    float* x2s  = smem + X2_OFF;
    float* outS = smem + OUTS_OFF;

    const int blk  = blockIdx.x;          // b*128 + h*2 + half
    const int b    = blk >> 7;
    const int h    = (blk >> 1) & 63;
    const int half = blk & 1;
    const int px0  = half * PXB;
    const int tid  = threadIdx.x;

    const int px   = tid >> 3;            // 0..31
    const int part = tid & 7;             // 0..7

    const size_t bbase = (size_t)b * HW;

    // this thread's logit set: k = part + 8*j
    float acc[7];
    int   nbrow[7];
    bool  valid[7];
#pragma unroll
    for (int j = 0; j < 7; j++) {
        acc[j] = 0.f;
        int k  = part + 8 * j;
        valid[j] = (k < NK);
        int kk = valid[j] ? k : 0;
        int dh = kk / 7, dw = kk - dh * 7;
        nbrow[j] = (dh * NCB + px + dw) * STR;
    }

    for (int cc = 0; cc < CH; cc += CHUNK) {
        // stage x1s: 32 px x 32 ch (one float4 per thread)
        {
            int p  = tid >> 3;
            int c4 = (tid & 7) << 2;
            float4 v = *(const float4*)(g_q + (bbase + (size_t)h * WID + px0 + p) * CH + cc + c4);
            *(float4*)(x1s + p * STR + c4) = v;
        }
        // stage x2s: 266 rows x 32 ch, zero-padded OOB
        for (int i = tid; i < X2ROWS * 8; i += 256) {
            int row = i >> 3;
            int c4  = (i & 7) << 2;
            int dh  = row / NCB;
            int col = row - dh * NCB;
            int hh  = h + dh - RAD;
            int gw  = px0 + col - RAD;
            float4 v = make_float4(0.f, 0.f, 0.f, 0.f);
            if (hh >= 0 && hh < HGT && gw >= 0 && gw < WID)
                v = *(const float4*)(g_k + (bbase + (size_t)hh * WID + gw) * CH + cc + c4);
            *(float4*)(x2s + row * STR + c4) = v;
        }
        __syncthreads();

        const float* x1p = x1s + px * STR;
#pragma unroll
        for (int c4 = 0; c4 < CHUNK; c4 += 4) {
            float4 qa = *(const float4*)(x1p + c4);
#pragma unroll
            for (int j = 0; j < 7; j++) {
                float4 kb = *(const float4*)(x2s + nbrow[j] + c4);
                acc[j] = fmaf(qa.x, kb.x, acc[j]);
                acc[j] = fmaf(qa.y, kb.y, acc[j]);
                acc[j] = fmaf(qa.z, kb.z, acc[j]);
                acc[j] = fmaf(qa.w, kb.w, acc[j]);
            }
        }
        __syncthreads();
    }

    // softmax across the 8-thread group owning pixel px
    float m = -1e30f;
#pragma unroll
    for (int j = 0; j < 7; j++)
        if (valid[j]) m = fmaxf(m, acc[j]);
    m = fmaxf(m, __shfl_xor_sync(0xffffffffu, m, 1));
    m = fmaxf(m, __shfl_xor_sync(0xffffffffu, m, 2));
    m = fmaxf(m, __shfl_xor_sync(0xffffffffu, m, 4));

    float e[7];
    float s = 0.f;
#pragma unroll
    for (int j = 0; j < 7; j++) {
        e[j] = valid[j] ? __expf(acc[j] - m) : 0.f;
        s += e[j];
    }
    s += __shfl_xor_sync(0xffffffffu, s, 1);
    s += __shfl_xor_sync(0xffffffffu, s, 2);
    s += __shfl_xor_sync(0xffffffffu, s, 4);
    float inv = 1.f / s;
#pragma unroll
    for (int j = 0; j < 7; j++) {
        int k = part + 8 * j;
        if (valid[j]) ws[px * WSTR + k] = e[j] * inv;
    }
    __syncthreads();

    // ---------------- Phase 2: thread = channel ----------------
    const int c = tid;
    float oacc[PXB];
#pragma unroll
    for (int i = 0; i < PXB; i++) oacc[i] = 0.f;

    for (int dh = 0; dh < 7; dh++) {
        int hh = h + dh - RAD;
        if (hh < 0 || hh >= HGT) continue;   // uniform branch
        const float* vrow = g_v + (bbase + (size_t)hh * WID) * CH + c;
        const float* wsp  = ws + dh * 7;
#pragma unroll
        for (int wg = 0; wg < NCB; wg++) {
            int gw = px0 + wg - RAD;
            float vv = (gw >= 0 && gw < WID) ? vrow[(size_t)gw * CH] : 0.f;
#pragma unroll
            for (int dw = 0; dw < 7; dw++) {
                int pl = wg - dw;             // compile-time per unrolled iter
                if (pl >= 0 && pl < PXB)
                    oacc[pl] = fmaf(wsp[pl * WSTR + dw], vv, oacc[pl]);
            }
        }
    }

    __syncthreads();                 // phase-1 tiles dead; safe to alias outS
#pragma unroll
    for (int i = 0; i < PXB; i++) outS[c * 33 + i] = oacc[i];
    __syncthreads();

    // coalesced store to [B,C,H,W]: 256 ch x 32 px
#pragma unroll
    for (int r = 0; r < 32; r++) {
        int idx = r * 256 + tid;
        int cch = idx >> 5;
        int w   = idx & 31;
        out[((size_t)(b * CH + cch) * HGT + h) * WID + px0 + w] = outS[cch * 33 + w];
    }
}

// ---------------------------------------------------------------------------
extern "C" void kernel_launch(void* const* d_in, const int* in_sizes, int n_in,
                              void* d_out, int out_size)
{
    const float* x  = (const float*)d_in[0];
    const float* w1 = (const float*)d_in[1];
    const float* w2 = (const float*)d_in[2];
    const float* w3 = (const float*)d_in[3];
    float* out = (float*)d_out;
    (void)in_sizes; (void)n_in; (void)out_size;

    cudaFuncSetAttribute(attn_kernel,
                         cudaFuncAttributeMaxDynamicSharedMemorySize,
                         SMEM_FLOATS * (int)sizeof(float));

    dim3 ggrid(HW / 128, CH / 64, BATCH * 3);
    gemm_kernel<<<ggrid, 256>>>(x, w1, w2, w3);

    attn_kernel<<<BATCH * HGT * 2, 256, SMEM_FLOATS * sizeof(float)>>>(out);
}

// round 5
// speedup vs baseline: 1.5513x; 1.5513x over previous
#include <cuda_runtime.h>
#include <math.h>

#define HGT   64
#define WID   64
#define CH    256
#define BATCH 4
#define HW    (HGT*WID)
#define RAD   3
#define NK    49
#define PXB   32          // pixels per block (half row)
#define NCB   (PXB+6)     // 38 neighborhood columns
#define X2ROWS (7*NCB)    // 266
#define CHUNK 16
#define STR   20          // smem row stride (floats) for 16-ch chunk
#define WSTR  52

// Pixel-major scratch: [B][HW][C]
__device__ float g_q[BATCH*HW*CH];
__device__ float g_k[BATCH*HW*CH];
__device__ float g_v[BATCH*HW*CH];

// ---------------------------------------------------------------------------
// GEMM: Yt[b][p][o] = sum_c X[b][c][p] * W[o][c]   (unchanged — ~85% fp32 peak)
// ---------------------------------------------------------------------------
__global__ __launch_bounds__(256) void gemm_kernel(
    const float* __restrict__ x,
    const float* __restrict__ w1,
    const float* __restrict__ w2,
    const float* __restrict__ w3)
{
    const int z    = blockIdx.z;
    const int b    = z / 3;
    const int wsel = z - b*3;
    const float* W = (wsel == 0) ? w1 : (wsel == 1 ? w2 : w3);
    float* Y       = (wsel == 0) ? g_q : (wsel == 1 ? g_k : g_v);
    const float* X = x + (size_t)b * CH * HW;
    Y += (size_t)b * HW * CH;

    const int p0 = blockIdx.x * 128;
    const int o0 = blockIdx.y * 64;

    __shared__ float As[16][128];
    __shared__ float Bs[16][68];

    const int tid = threadIdx.x;
    const int tx  = tid & 15;
    const int ty  = tid >> 4;

    float acc[8][4];
#pragma unroll
    for (int i = 0; i < 8; i++)
#pragma unroll
        for (int j = 0; j < 4; j++) acc[i][j] = 0.f;

    for (int k0 = 0; k0 < CH; k0 += 16) {
#pragma unroll
        for (int r = 0; r < 2; r++) {
            int idx = tid + r * 256;
            int cr  = idx >> 5;
            int p4  = (idx & 31) << 2;
            float4 v = *(const float4*)(X + (size_t)(k0 + cr) * HW + p0 + p4);
            *(float4*)(&As[cr][p4]) = v;
        }
        {
            int oo  = tid >> 2;
            int kk4 = (tid & 3) << 2;
            float4 v = *(const float4*)(W + (size_t)(o0 + oo) * CH + k0 + kk4);
            Bs[kk4 + 0][oo] = v.x;
            Bs[kk4 + 1][oo] = v.y;
            Bs[kk4 + 2][oo] = v.z;
            Bs[kk4 + 3][oo] = v.w;
        }
        __syncthreads();

#pragma unroll
        for (int kk = 0; kk < 16; kk++) {
            float a[8], bb[4];
            float4 a0 = *(const float4*)(&As[kk][ty * 8]);
            float4 a1 = *(const float4*)(&As[kk][ty * 8 + 4]);
            a[0]=a0.x; a[1]=a0.y; a[2]=a0.z; a[3]=a0.w;
            a[4]=a1.x; a[5]=a1.y; a[6]=a1.z; a[7]=a1.w;
            float4 b0 = *(const float4*)(&Bs[kk][tx * 4]);
            bb[0]=b0.x; bb[1]=b0.y; bb[2]=b0.z; bb[3]=b0.w;
#pragma unroll
            for (int i = 0; i < 8; i++)
#pragma unroll
                for (int j = 0; j < 4; j++)
                    acc[i][j] = fmaf(a[i], bb[j], acc[i][j]);
        }
        __syncthreads();
    }

#pragma unroll
    for (int i = 0; i < 8; i++) {
        float4 v = make_float4(acc[i][0], acc[i][1], acc[i][2], acc[i][3]);
        *(float4*)(Y + (size_t)(p0 + ty * 8 + i) * CH + o0 + tx * 4) = v;
    }
}

// ---------------------------------------------------------------------------
// Attention: block = (b, h, half-row of 32 px). 256 threads, 30.5KB static smem.
// Phase 1: 16-ch chunks, register-double-buffered staging, 8 threads/pixel.
// Phase 2: thread = channel, two passes of 16 register accumulators.
// smem floats: ws[32*52]=1664 | x1s[32*20]=640 | x2s[266*20]=5320  (=7624)
//              outS[256*20]=5120 aliases x1s+x2s.
// ---------------------------------------------------------------------------
#define WS_OFF   0
#define X1_OFF   1664
#define X2_OFF   (1664 + PXB*STR)       // 2304
#define OUTS_OFF 1664
#define SMEM_FLOATS (1664 + PXB*STR + X2ROWS*STR)   // 7624
#define NUNITS   (PXB*4 + X2ROWS*4)     // 1192 float4 staging units per chunk

__global__ __launch_bounds__(256) void attn_kernel(float* __restrict__ out)
{
    __shared__ float smem[SMEM_FLOATS];
    float* ws   = smem + WS_OFF;
    float* outS = smem + OUTS_OFF;

    const int blk  = blockIdx.x;          // b*128 + h*2 + half
    const int b    = blk >> 7;
    const int h    = (blk >> 1) & 63;
    const int half = blk & 1;
    const int px0  = half * PXB;
    const int tid  = threadIdx.x;

    const int px   = tid >> 3;            // 0..31
    const int part = tid & 7;             // 0..7

    const size_t bbase = (size_t)b * HW;

    // ---- staging plan: 5 float4 units per thread, computed once ----
    const float* gp[5];
    int so[5];
#pragma unroll
    for (int it = 0; it < 5; it++) {
        int unit = tid + it * 256;
        gp[it] = 0; so[it] = -1;
        if (unit < PXB * 4) {
            int p  = unit >> 2;
            int c4 = (unit & 3) << 2;
            gp[it] = g_q + (bbase + (size_t)h * WID + px0 + p) * CH + c4;
            so[it] = X1_OFF + p * STR + c4;
        } else if (unit < NUNITS) {
            int u   = unit - PXB * 4;
            int row = u >> 2;
            int c4  = (u & 3) << 2;
            int dh  = row / NCB;
            int col = row - dh * NCB;
            int hh  = h + dh - RAD;
            int gw  = px0 + col - RAD;
            so[it] = X2_OFF + row * STR + c4;
            if (hh >= 0 && hh < HGT && gw >= 0 && gw < WID)
                gp[it] = g_k + (bbase + (size_t)hh * WID + gw) * CH + c4;
        }
    }

    // ---- per-thread logit rows ----
    float acc[7];
    int   nbrow[7];
#pragma unroll
    for (int j = 0; j < 7; j++) {
        acc[j] = 0.f;
        int k  = part + 8 * j;
        int kk = (k < NK) ? k : 0;
        int dh = kk / 7, dw = kk - dh * 7;
        nbrow[j] = X2_OFF + (dh * NCB + px + dw) * STR;
    }

    // ---- prologue: load chunk 0 into registers ----
    float4 rg[5];
#pragma unroll
    for (int it = 0; it < 5; it++) {
        rg[it] = make_float4(0.f, 0.f, 0.f, 0.f);
        if (so[it] >= 0 && gp[it]) rg[it] = *(const float4*)(gp[it]);
    }

    const float* x1p = smem + X1_OFF + px * STR;

    for (int ch = 0; ch < CH / CHUNK; ch++) {
        // commit current chunk to smem
#pragma unroll
        for (int it = 0; it < 5; it++)
            if (so[it] >= 0) *(float4*)(smem + so[it]) = rg[it];
        __syncthreads();

        // prefetch next chunk into registers (latency overlapped with compute)
        if (ch + 1 < CH / CHUNK) {
            int cco = (ch + 1) * CHUNK;
#pragma unroll
            for (int it = 0; it < 5; it++) {
                rg[it] = make_float4(0.f, 0.f, 0.f, 0.f);
                if (so[it] >= 0 && gp[it]) rg[it] = *(const float4*)(gp[it] + cco);
            }
        }

        // compute logit partial sums from smem
#pragma unroll
        for (int c4 = 0; c4 < CHUNK; c4 += 4) {
            float4 qa = *(const float4*)(x1p + c4);
#pragma unroll
            for (int j = 0; j < 7; j++) {
                float4 kb = *(const float4*)(smem + nbrow[j] + c4);
                acc[j] = fmaf(qa.x, kb.x, acc[j]);
                acc[j] = fmaf(qa.y, kb.y, acc[j]);
                acc[j] = fmaf(qa.z, kb.z, acc[j]);
                acc[j] = fmaf(qa.w, kb.w, acc[j]);
            }
        }
        __syncthreads();
    }

    // ---- softmax across the 8-thread group owning pixel px ----
    float m = -1e30f;
#pragma unroll
    for (int j = 0; j < 7; j++)
        if (part + 8 * j < NK) m = fmaxf(m, acc[j]);
    m = fmaxf(m, __shfl_xor_sync(0xffffffffu, m, 1));
    m = fmaxf(m, __shfl_xor_sync(0xffffffffu, m, 2));
    m = fmaxf(m, __shfl_xor_sync(0xffffffffu, m, 4));

    float e[7];
    float s = 0.f;
#pragma unroll
    for (int j = 0; j < 7; j++) {
        int k = part + 8 * j;
        e[j] = (k < NK) ? __expf(acc[j] - m) : 0.f;
        s += e[j];
    }
    s += __shfl_xor_sync(0xffffffffu, s, 1);
    s += __shfl_xor_sync(0xffffffffu, s, 2);
    s += __shfl_xor_sync(0xffffffffu, s, 4);
    float inv = 1.f / s;
#pragma unroll
    for (int j = 0; j < 7; j++) {
        int k = part + 8 * j;
        if (k < NK) ws[px * WSTR + k] = e[j] * inv;
    }
    __syncthreads();

    // ---- Phase 2: thread = channel; two passes of 16 pixels ----
    const int c = tid;
#pragma unroll 1
    for (int hv = 0; hv < 2; hv++) {
        const int p0h = px0 + hv * 16;   // global first pixel of this pass
        const int pl0 = hv * 16;         // block-local first pixel

        float oacc[16];
#pragma unroll
        for (int i = 0; i < 16; i++) oacc[i] = 0.f;

        for (int dh = 0; dh < 7; dh++) {
            int hh = h + dh - RAD;
            if (hh < 0 || hh >= HGT) continue;          // uniform branch
            const float* vrow = g_v + (bbase + (size_t)hh * WID) * CH + c;
            const float* wsp  = ws + pl0 * WSTR + dh * 7;
#pragma unroll
            for (int wg = 0; wg < 22; wg++) {           // 16 + 6 neighborhood cols
                int gw = p0h + wg - RAD;
                float vv = (gw >= 0 && gw < WID) ? vrow[(size_t)gw * CH] : 0.f;
#pragma unroll
                for (int dw = 0; dw < 7; dw++) {
                    int pl = wg - dw;                   // compile-time per iter
                    if (pl >= 0 && pl < 16)
                        oacc[pl] = fmaf(wsp[pl * WSTR + dw], vv, oacc[pl]);
                }
            }
        }

        // transpose through smem for coalesced stores
#pragma unroll
        for (int i = 0; i < 16; i++) outS[c * STR + i] = oacc[i];
        __syncthreads();

#pragma unroll
        for (int r4 = 0; r4 < 4; r4++) {
            int idx = tid + r4 * 256;     // 0..1023 float4 units
            int cch = idx >> 2;
            int w4  = (idx & 3) << 2;
            float4 v = *(const float4*)(outS + cch * STR + w4);
            *(float4*)(out + ((size_t)(b * CH + cch) * HGT + h) * WID + p0h + w4) = v;
        }
        __syncthreads();
    }
}

// ---------------------------------------------------------------------------
extern "C" void kernel_launch(void* const* d_in, const int* in_sizes, int n_in,
                              void* d_out, int out_size)
{
    const float* x  = (const float*)d_in[0];
    const float* w1 = (const float*)d_in[1];
    const float* w2 = (const float*)d_in[2];
    const float* w3 = (const float*)d_in[3];
    float* out = (float*)d_out;
    (void)in_sizes; (void)n_in; (void)out_size;

    dim3 ggrid(HW / 128, CH / 64, BATCH * 3);
    gemm_kernel<<<ggrid, 256>>>(x, w1, w2, w3);

    attn_kernel<<<BATCH * HGT * 2, 256>>>(out);
}